// round 2
// baseline (speedup 1.0000x reference)
#include <cuda_runtime.h>
#include <cstdint>

// Problem constants
#define NN 16      // N (both u and v)
#define CC 4       // C
#define HH 32
#define WW 32
#define SS 1024    // H*W
#define K2 9       // 3x3
#define EE 144     // C*C*K2 floats per (u,v,s) chunk
#define ST 4       // s-values per block
#define VB 8       // v-values per block
#define NLANES 36  // EE/4 quads
#define NTHREADS (VB * NLANES)  // 288

// ---- packed f32x2 helpers ----
__device__ __forceinline__ unsigned long long ffma2(unsigned long long a,
                                                    unsigned long long b,
                                                    unsigned long long c) {
    unsigned long long d;
    asm("fma.rn.f32x2 %0, %1, %2, %3;" : "=l"(d) : "l"(a), "l"(b), "l"(c));
    return d;
}
__device__ __forceinline__ unsigned long long fmul2(unsigned long long a,
                                                    unsigned long long b) {
    unsigned long long d;
    asm("mul.rn.f32x2 %0, %1, %2;" : "=l"(d) : "l"(a), "l"(b));
    return d;
}
__device__ __forceinline__ unsigned long long pack2(float lo, float hi) {
    unsigned long long d;
    asm("mov.b64 %0, {%1, %2};" : "=l"(d) : "f"(lo), "f"(hi));
    return d;
}

__global__ __launch_bounds__(NTHREADS)
void plastic_edges_kernel(const float* __restrict__ x,
                          const float* __restrict__ weight,
                          const float* __restrict__ chan_map,
                          const float* __restrict__ mask,
                          float* __restrict__ out) {
    // x_sh: x_unfold values replicated across o: [u(16)][sl(ST)][p(144)]
    // reused after the main loop as the c-reduction buffer red[VB][ST][144]
    __shared__ __align__(16) float x_sh[16 * ST * EE];       // 9216 floats = 36864 B
    __shared__ float cm_sh[16 * VB * 16];                    // 2048 floats = 8192 B

    const int t     = threadIdx.x;
    const int bs0   = blockIdx.x * ST;       // s tile base
    const int vbase = blockIdx.y * VB;       // v tile base
    const int vl    = t / NLANES;            // 0..7
    const int lane  = t % NLANES;            // 0..35 (quad index)
    const int v     = vbase + vl;

    // ---- stage cm_sh[u][vl][c*4+o] = chan_map[u,v,c,o] * mask[u,v] ----
    for (int i = t; i < 16 * VB * 16; i += NTHREADS) {
        int u   = i >> 7;        // / (VB*16)
        int r   = i & 127;
        int vli = r >> 4;
        int co  = r & 15;
        int uv  = u * NN + (vbase + vli);
        cm_sh[i] = chan_map[uv * 16 + co] * mask[uv];
    }

    // ---- stage x_sh[u][sl][p] = x_unf[u, bs0+sl, c(p), k(p)]  (o-replicated) ----
    {
        int p  = t % EE;         // fixed per thread -> decode once
        int c  = p / 36;
        int k  = p % 9;          // p = c*36 + o*9 + k  ->  p%9 == k
        int ki = k / 3, kj = k % 3;
        for (int r = t / EE; r < 16 * ST; r += NTHREADS / EE) {  // 2 threads per p
            int u  = r >> 2;     // / ST
            int sl = r & (ST - 1);
            int s  = bs0 + sl;
            int h  = s >> 5, w = s & 31;
            int y  = h + ki - 1, xx = w + kj - 1;
            float val = 0.0f;
            if ((unsigned)y < 32u && (unsigned)xx < 32u)
                val = x[((u * CC + c) * HH + y) * WW + xx];
            x_sh[(u * ST + sl) * EE + p] = val;
        }
    }
    __syncthreads();

    // per-thread cm gather indices for this quad (p = lane*4 + e)
    int cmi[4];
#pragma unroll
    for (int e = 0; e < 4; e++) {
        int p  = lane * 4 + e;
        int c  = p / 36;
        int o  = (p % 36) / 9;
        cmi[e] = c * 4 + o;
    }

    // accumulators: mapped[v, bs0+sl, o(p), k(p)] partial (sum over u; c summed later)
    unsigned long long acc[ST][2];
#pragma unroll
    for (int sl = 0; sl < ST; sl++) { acc[sl][0] = 0ull; acc[sl][1] = 0ull; }

    const long ustride = (long)NN * SS * EE;  // elements between consecutive u
    const float* wb0 = weight + ((long)v * SS + bs0) * EE + lane * 4;

#pragma unroll 4
    for (int u = 0; u < 16; u++) {
        const float* wb = wb0 + (long)u * ustride;
        const float* cmb = &cm_sh[(u * VB + vl) * 16];
        unsigned long long cm01 = pack2(cmb[cmi[0]], cmb[cmi[1]]);
        unsigned long long cm23 = pack2(cmb[cmi[2]], cmb[cmi[3]]);
        unsigned xs0 = (unsigned)__cvta_generic_to_shared(&x_sh[(u * ST) * EE + lane * 4]);
#pragma unroll
        for (int sl = 0; sl < ST; sl++) {
            unsigned long long w01, w23, x01, x23;
            // streaming load: weight is read exactly once -> evict-first
            asm("ld.global.cs.v2.b64 {%0,%1}, [%2];"
                : "=l"(w01), "=l"(w23) : "l"(wb + sl * EE));
            asm volatile("ld.shared.v2.b64 {%0,%1}, [%2];"
                : "=l"(x01), "=l"(x23) : "r"(xs0 + sl * (EE * 4)));
            acc[sl][0] = ffma2(w01, fmul2(x01, cm01), acc[sl][0]);
            acc[sl][1] = ffma2(w23, fmul2(x23, cm23), acc[sl][1]);
        }
    }

    // ---- c-reduction via shared, then fused fold scatter ----
    __syncthreads();   // all x_sh reads done; safe to reuse as red[]
    float* red = x_sh; // [vl][sl][p], VB*ST*EE = 4608 floats <= 9216
#pragma unroll
    for (int sl = 0; sl < ST; sl++) {
        ulonglong2 pk; pk.x = acc[sl][0]; pk.y = acc[sl][1];
        *(ulonglong2*)&red[(vl * ST + sl) * EE + lane * 4] = pk;
    }
    __syncthreads();

    // outputs: VB*ST*36 = 1152 (o,k) results; sum 4 c-slices each; fold-scatter
    for (int r = t; r < VB * ST * 36; r += NTHREADS) {
        int vli = r / (ST * 36);
        int q   = r % (ST * 36);
        int sl  = q / 36;
        int ok  = q % 36;            // o*9 + k
        int o   = ok / 9, k = ok % 9;
        const float* rb = &red[(vli * ST + sl) * EE + ok];
        float val = rb[0] + rb[36] + rb[72] + rb[108];
        // fold: channel index ch = k*C + o, decoded by fold as (cf, fi, fj)
        int ch  = k * CC + o;
        int cf  = ch / 9;
        int rem = ch % 9;
        int fi  = rem / 3, fj = rem % 3;
        int s = bs0 + sl;
        int h = s >> 5, w = s & 31;
        int y = h + fi - 1, xx = w + fj - 1;
        if ((unsigned)y < 32u && (unsigned)xx < 32u)
            atomicAdd(&out[(((vbase + vli) * CC + cf) * HH + y) * WW + xx], val);
    }
}

extern "C" void kernel_launch(void* const* d_in, const int* in_sizes, int n_in,
                              void* d_out, int out_size) {
    // identify inputs by element count (robust to ordering)
    const float *x = nullptr, *wt = nullptr, *cm = nullptr, *mk = nullptr;
    for (int i = 0; i < n_in; i++) {
        switch (in_sizes[i]) {
            case NN * CC * HH * WW:                       x  = (const float*)d_in[i]; break; // 65536
            case NN * NN * SS * CC * CC * K2:             wt = (const float*)d_in[i]; break; // 37748736
            case NN * NN * CC * CC:                       cm = (const float*)d_in[i]; break; // 4096
            case NN * NN:                                 mk = (const float*)d_in[i]; break; // 256
            default: break;
        }
    }
    float* out = (float*)d_out;

    cudaMemsetAsync(out, 0, (size_t)out_size * sizeof(float), 0);

    dim3 grid(SS / ST, NN / VB);   // (256, 2) = 512 blocks
    plastic_edges_kernel<<<grid, NTHREADS, 0, 0>>>(x, wt, cm, mk, out);
}